// round 6
// baseline (speedup 1.0000x reference)
#include <cuda_runtime.h>

// DisentangledSelfAttention, fully fused fp32, f32x2 packed FMA.
// 2 batch elements per CTA (grid 2048), 256 threads, 8x4 thread tiles over
// stacked [128,64] GEMMs. All operands in smem (LD=64), KhT stored transposed
// (stride 132) so every GEMM is nn with conflict-free loads.

#define ULL unsigned long long

__device__ __forceinline__ ULL pk2(float x, float y) {
    ULL r;
    asm("mov.b64 %0, {%1, %2};" : "=l"(r) : "f"(x), "f"(y));
    return r;
}
__device__ __forceinline__ void fma2(ULL& d, ULL a, ULL b) {
    asm("fma.rn.f32x2 %0, %1, %2, %0;" : "+l"(d) : "l"(a), "l"(b));
}
__device__ __forceinline__ float2 upk(ULL v) {
    float2 r;
    asm("mov.b64 {%0, %1}, %2;" : "=f"(r.x), "=f"(r.y) : "l"(v));
    return r;
}

// acc[p][j]: packed pair = rows (R+2p, R+2p+1), col C+j.
// A row-major stride 64; B row-major stride ldb.
__device__ __forceinline__ void gemm8x4(const float* __restrict__ A,
                                        const float* __restrict__ B, int ldb,
                                        ULL acc[4][4], int R, int C) {
#pragma unroll
    for (int k = 0; k < 64; k += 4) {
        float4 a[8];
#pragma unroll
        for (int i = 0; i < 8; i++) a[i] = *(const float4*)&A[(R + i) * 64 + k];
#pragma unroll
        for (int kk = 0; kk < 4; kk++) {
            float4 b4 = *(const float4*)&B[(k + kk) * ldb + C];
            ULL bd0 = pk2(b4.x, b4.x), bd1 = pk2(b4.y, b4.y);
            ULL bd2 = pk2(b4.z, b4.z), bd3 = pk2(b4.w, b4.w);
#pragma unroll
            for (int p = 0; p < 4; p++) {
                const float* alo = (const float*)&a[2 * p];
                const float* ahi = (const float*)&a[2 * p + 1];
                ULL ap = pk2(alo[kk], ahi[kk]);
                fma2(acc[p][0], ap, bd0);
                fma2(acc[p][1], ap, bd1);
                fma2(acc[p][2], ap, bd2);
                fma2(acc[p][3], ap, bd3);
            }
        }
    }
}

__device__ __forceinline__ void init_tile(ULL acc[4][4], float v0, float v1,
                                          float v2, float v3) {
    ULL a0 = pk2(v0, v0), a1 = pk2(v1, v1), a2 = pk2(v2, v2), a3 = pk2(v3, v3);
#pragma unroll
    for (int p = 0; p < 4; p++) {
        acc[p][0] = a0; acc[p][1] = a1; acc[p][2] = a2; acc[p][3] = a3;
    }
}

__device__ __forceinline__ void store_tile(float* __restrict__ dst,
                                           ULL acc[4][4], int R, int C) {
#pragma unroll
    for (int p = 0; p < 4; p++) {
        float2 c0 = upk(acc[p][0]), c1 = upk(acc[p][1]);
        float2 c2 = upk(acc[p][2]), c3 = upk(acc[p][3]);
        *(float4*)&dst[(R + 2 * p) * 64 + C]     = make_float4(c0.x, c1.x, c2.x, c3.x);
        *(float4*)&dst[(R + 2 * p + 1) * 64 + C] = make_float4(c0.y, c1.y, c2.y, c3.y);
    }
}

// dst[e*64 + c] = W[e*256 + hc + c],  e,c in [0,64)
__device__ __forceinline__ void stage_w(float* __restrict__ dst,
                                        const float* __restrict__ W,
                                        int hc, int tid) {
#pragma unroll
    for (int it = 0; it < 4; it++) {
        int i = tid + (it << 8);
        int e = i >> 4, c = (i & 15) << 2;
        *(float4*)&dst[(e << 6) + c] = *(const float4*)&W[(e << 8) + hc + c];
    }
}

// smem offsets (floats)
#define O_QIN  0
#define O_KIN  8192
#define O_VIN  16384
#define O_W    24576
#define O_QH   28672
#define O_KHT  36864        // [64][132]
#define O_VH   45312
#define O_MQ   53504        // [2][64]
#define O_QC   53632        // [2][256]
#define O_USM  54144        // [2][4][64]
#define O_WU   54656        // [64][4]
#define SM_FLOATS 54912

__global__ __launch_bounds__(256, 1)
void disattn_kernel(const float* __restrict__ query,
                    const float* __restrict__ key_,
                    const float* __restrict__ value,
                    const float* __restrict__ Wq, const float* __restrict__ bq,
                    const float* __restrict__ Wk, const float* __restrict__ bk,
                    const float* __restrict__ Wv, const float* __restrict__ bv,
                    const float* __restrict__ Wu, const float* __restrict__ bu,
                    const float* __restrict__ Wr, const float* __restrict__ br,
                    float* __restrict__ out) {
    extern __shared__ float sm[];
    float* sQin = sm + O_QIN;
    float* sKin = sm + O_KIN;
    float* sVin = sm + O_VIN;
    float* sW   = sm + O_W;
    float* sQh  = sm + O_QH;    // Q-head, then scores/attn
    float* sKhT = sm + O_KHT;   // K-head transposed [d][s], stride 132
    float* sVh  = sm + O_VH;
    float* mq   = sm + O_MQ;
    float* qc   = sm + O_QC;
    float* susm = sm + O_USM;
    float* sWu  = sm + O_WU;

    const int tid = threadIdx.x;
    const int b0 = blockIdx.x << 1;
    const int tx = tid & 15, ty = tid >> 4;
    const int R = ty << 3, C = tx << 2;
    const int batch = R >> 6;            // 0 or 1

    const float* qg = query + (size_t)b0 * 4096;
    const float* kg = key_  + (size_t)b0 * 4096;
    const float* vg = value + (size_t)b0 * 4096;

    // Stage inputs (2 batches contiguous = 8192 floats each) + Wu.
#pragma unroll
    for (int it = 0; it < 8; it++) {
        int i4 = (tid + (it << 8)) << 2;
        *(float4*)&sQin[i4] = *(const float4*)&qg[i4];
        *(float4*)&sKin[i4] = *(const float4*)&kg[i4];
        *(float4*)&sVin[i4] = *(const float4*)&vg[i4];
    }
    if (tid < 64)
        *(float4*)&sWu[tid << 2] = *(const float4*)&Wu[tid << 2];
    __syncthreads();

    // Unary logits u[b][h][s] (rotated float4 reads) + query row-means mq[b][e].
#pragma unroll
    for (int u = 0; u < 2; u++) {
        int slot = tid + (u << 8);
        int s = slot & 63, h = (slot >> 6) & 3, bb = slot >> 8;
        const float* kr = &sKin[((bb << 6) + s) << 6];
        float acc = __ldg(&bu[h]);
#pragma unroll
        for (int cc = 0; cc < 16; cc++) {
            int c4 = ((cc + s) & 15) << 2;
            float4 kv = *(const float4*)&kr[c4];
            acc = fmaf(kv.x, sWu[((c4 + 0) << 2) + h], acc);
            acc = fmaf(kv.y, sWu[((c4 + 1) << 2) + h], acc);
            acc = fmaf(kv.z, sWu[((c4 + 2) << 2) + h], acc);
            acc = fmaf(kv.w, sWu[((c4 + 3) << 2) + h], acc);
        }
        susm[((bb << 2) + h) * 64 + s] = acc;
    }
    if (tid < 128) {
        int bb = tid >> 6, e = tid & 63;
        float s = 0.0f;
#pragma unroll
        for (int r = 0; r < 64; r++) s += sQin[((bb << 6) + r) * 64 + e];
        mq[tid] = s * (1.0f / 64.0f);
    }
    __syncthreads();

    // Unary softmax over s, one warp per (b,h).
    {
        int w = tid >> 5, lane = tid & 31;
        float v0 = susm[(w << 6) + lane];
        float v1 = susm[(w << 6) + 32 + lane];
        float m = fmaxf(v0, v1);
#pragma unroll
        for (int d = 16; d; d >>= 1)
            m = fmaxf(m, __shfl_xor_sync(0xffffffffu, m, d));
        float e0 = __expf(v0 - m), e1 = __expf(v1 - m);
        float s2 = e0 + e1;
#pragma unroll
        for (int d = 16; d; d >>= 1)
            s2 += __shfl_xor_sync(0xffffffffu, s2, d);
        float inv = 1.0f / s2;
        susm[(w << 6) + lane]      = e0 * inv;
        susm[(w << 6) + 32 + lane] = e1 * inv;
    }
    __syncthreads();

    // qc[b][a] = mq[b] @ Wq[:,a]  (Q-centering; bq cancels exactly)
#pragma unroll
    for (int u = 0; u < 2; u++) {
        int slot = tid + (u << 8);
        int bb = slot >> 8, aa = slot & 255;
        const float* mqb = &mq[bb << 6];
        float acc = 0.0f;
#pragma unroll
        for (int e = 0; e < 64; e++)
            acc = fmaf(mqb[e], __ldg(&Wq[(e << 8) + aa]), acc);
        qc[slot] = acc;
    }
    __syncthreads();

#pragma unroll 1
    for (int h = 0; h < 4; h++) {
        const int hc = h << 6;

        // Q-head (centered): qin @ WqSlice - qc
        stage_w(sW, Wq, hc, tid);
        __syncthreads();
        {
            ULL acc[4][4];
            const float* qcb = &qc[(batch << 8) + hc + C];
            init_tile(acc, -qcb[0], -qcb[1], -qcb[2], -qcb[3]);
            gemm8x4(sQin, sW, 64, acc, R, C);
            store_tile(sQh, acc, R, C);
        }
        __syncthreads();

        // K-head (no bias, no centering needed) -> transposed store
        stage_w(sW, Wk, hc, tid);
        __syncthreads();
        {
            ULL acc[4][4];
            init_tile(acc, 0.0f, 0.0f, 0.0f, 0.0f);
            gemm8x4(sKin, sW, 64, acc, R, C);
#pragma unroll
            for (int p = 0; p < 4; p++)
#pragma unroll
                for (int j = 0; j < 4; j++) {
                    float2 v = upk(acc[p][j]);
                    *(float2*)&sKhT[(C + j) * 132 + R + 2 * p] = v;
                }
        }
        __syncthreads();

        // V-head (+ bv)
        stage_w(sW, Wv, hc, tid);
        __syncthreads();
        {
            ULL acc[4][4];
            init_tile(acc, __ldg(&bv[hc + C + 0]), __ldg(&bv[hc + C + 1]),
                      __ldg(&bv[hc + C + 2]), __ldg(&bv[hc + C + 3]));
            gemm8x4(sVin, sW, 64, acc, R, C);
            store_tile(sVh, acc, R, C);
        }
        __syncthreads();

        // scores = Qt @ K^T  (per batch), into registers
        ULL sacc[4][4];
        init_tile(sacc, 0.0f, 0.0f, 0.0f, 0.0f);
        gemm8x4(sQh, sKhT + (batch << 6), 132, sacc, R, C);
        __syncthreads();                    // all Qh/KhT reads complete
        store_tile(sQh, sacc, R, C);        // scores overwrite Qh
        stage_w(sW, Wr, hc, tid);           // Wr slice (sW is dead)
        __syncthreads();

        // Row softmax + unary add (2 threads/row, rotated float4 access)
        {
            int row = tid >> 1, half = tid & 1;
            int bb2 = row >> 6;
            float* sr = &sQh[(row << 6) + (half << 5)];
            const float* ur = &susm[((bb2 << 2) + h) << 6] + (half << 5);
            int rot = row & 7;
            float4 v[8];
#pragma unroll
            for (int cc = 0; cc < 8; cc++) {
                int c4 = ((cc + rot) & 7) << 2;
                v[cc] = *(const float4*)&sr[c4];
            }
            float m = -1e30f;
#pragma unroll
            for (int cc = 0; cc < 8; cc++) {
                m = fmaxf(m, fmaxf(fmaxf(v[cc].x, v[cc].y), fmaxf(v[cc].z, v[cc].w)));
            }
            m = fmaxf(m, __shfl_xor_sync(0xffffffffu, m, 1));
            float ssum = 0.0f;
#pragma unroll
            for (int cc = 0; cc < 8; cc++) {
                v[cc].x = __expf(v[cc].x - m);
                v[cc].y = __expf(v[cc].y - m);
                v[cc].z = __expf(v[cc].z - m);
                v[cc].w = __expf(v[cc].w - m);
                ssum += v[cc].x + v[cc].y + v[cc].z + v[cc].w;
            }
            ssum += __shfl_xor_sync(0xffffffffu, ssum, 1);
            float inv = 1.0f / ssum;
#pragma unroll
            for (int cc = 0; cc < 8; cc++) {
                int c4 = ((cc + rot) & 7) << 2;
                float4 u4 = *(const float4*)&ur[c4];
                float4 o;
                o.x = fmaf(v[cc].x, inv, u4.x);
                o.y = fmaf(v[cc].y, inv, u4.y);
                o.z = fmaf(v[cc].z, inv, u4.z);
                o.w = fmaf(v[cc].w, inv, u4.w);
                *(float4*)&sr[c4] = o;
            }
        }
        __syncthreads();

        // out = attn @ Vh + qin @ WrSlice + br
        {
            ULL acc[4][4];
            init_tile(acc, __ldg(&br[hc + C + 0]), __ldg(&br[hc + C + 1]),
                      __ldg(&br[hc + C + 2]), __ldg(&br[hc + C + 3]));
            gemm8x4(sQh, sVh + (batch << 12), 64, acc, R, C);
            gemm8x4(sQin, sW, 64, acc, R, C);

            float* og = out + (size_t)(b0 + batch) * 16384 + (R & 63) * 256 + hc + C;
#pragma unroll
            for (int p = 0; p < 4; p++) {
                float2 c0 = upk(acc[p][0]), c1 = upk(acc[p][1]);
                float2 c2 = upk(acc[p][2]), c3 = upk(acc[p][3]);
                *(float4*)&og[(2 * p) * 256]     = make_float4(c0.x, c1.x, c2.x, c3.x);
                *(float4*)&og[(2 * p + 1) * 256] = make_float4(c0.y, c1.y, c2.y, c3.y);
            }
        }
        __syncthreads();
    }
}

extern "C" void kernel_launch(void* const* d_in, const int* in_sizes, int n_in,
                              void* d_out, int out_size) {
    const float* query = (const float*)d_in[0];
    const float* key_  = (const float*)d_in[1];
    const float* value = (const float*)d_in[2];
    const float* Wq    = (const float*)d_in[3];
    const float* bq    = (const float*)d_in[4];
    const float* Wk    = (const float*)d_in[5];
    const float* bk    = (const float*)d_in[6];
    const float* Wv    = (const float*)d_in[7];
    const float* bv    = (const float*)d_in[8];
    const float* Wu    = (const float*)d_in[9];
    const float* bu    = (const float*)d_in[10];
    const float* Wr    = (const float*)d_in[11];
    const float* br    = (const float*)d_in[12];
    float* out = (float*)d_out;
    (void)bq; (void)bk;

    size_t smem = SM_FLOATS * sizeof(float);   // ~214.5 KB
    cudaFuncSetAttribute(disattn_kernel,
                         cudaFuncAttributeMaxDynamicSharedMemorySize, (int)smem);
    disattn_kernel<<<2048, 256, smem>>>(query, key_, value, Wq, bq, Wk, bk,
                                        Wv, bv, Wu, bu, Wr, br, out);
}